// round 3
// baseline (speedup 1.0000x reference)
#include <cuda_runtime.h>

#define B 512
#define N 256
#define E_PER 8192
#define NT (B*N)        // 131072 nodes
#define ET (B*E_PER)    // 4194304 edges
#define FIN 128
#define H 32
#define K 16
#define FOUT 10
#define EPSF 1e-15f

// ---------------- scratch (device globals; no allocation) ----------------
__device__ float g_h1[NT*H];     // lin1 output
__device__ float g_hc[NT*H];     // conv1 output
__device__ float g_s[NT*K];      // softmax cluster assignment
__device__ float g_t[NT*K];      // t = adj @ s
__device__ int   g_deg[NT];
__device__ int   g_cursor[NT];
__device__ int   g_sorted[ET];   // dst ids grouped by src (per-graph segments)
__device__ float g_loss[2*B];

// ---------------- kernels ----------------

__global__ void k_zero() {
    int i = blockIdx.x * blockDim.x + threadIdx.x;
    if (i < NT) g_deg[i] = 0;
}

// h1 = x @ W1 + b1 ; warp per node row, lane = output channel
__global__ void k_lin1(const float* __restrict__ x,
                       const float* __restrict__ W,
                       const float* __restrict__ b) {
    __shared__ float Ws[FIN*H];
    __shared__ float bs[H];
    for (int i = threadIdx.x; i < FIN*H; i += blockDim.x) Ws[i] = W[i];
    if (threadIdx.x < H) bs[threadIdx.x] = b[threadIdx.x];
    __syncthreads();
    int warp = (blockIdx.x * blockDim.x + threadIdx.x) >> 5;
    int lane = threadIdx.x & 31;
    if (warp >= NT) return;
    const float* xr = x + (size_t)warp * FIN;
    float xv[4];
#pragma unroll
    for (int i = 0; i < 4; i++) xv[i] = xr[i*32 + lane];
    float acc = bs[lane];
#pragma unroll
    for (int k = 0; k < FIN; k++) {
        float xk = __shfl_sync(0xffffffffu, xv[k >> 5], k & 31);
        acc += xk * Ws[k*H + lane];
    }
    g_h1[(size_t)warp*H + lane] = acc;
}

__global__ void k_count(const int* __restrict__ ei) {
    int e = blockIdx.x * blockDim.x + threadIdx.x;
    if (e < ET) atomicAdd(&g_deg[ei[e]], 1);
}

// per-graph exclusive scan of degrees -> cursor start offsets
__global__ void k_scan() {
    __shared__ int sd[N];
    int b = blockIdx.x, t = threadIdx.x;
    int d = g_deg[b*N + t];
    sd[t] = d;
    __syncthreads();
    for (int off = 1; off < N; off <<= 1) {
        int v = (t >= off) ? sd[t - off] : 0;
        __syncthreads();
        sd[t] += v;
        __syncthreads();
    }
    g_cursor[b*N + t] = b*E_PER + sd[t] - d;
}

__global__ void k_scatter(const int* __restrict__ ei) {
    int e = blockIdx.x * blockDim.x + threadIdx.x;
    if (e < ET) {
        int u = ei[e];
        int v = ei[ET + e];
        int p = atomicAdd(&g_cursor[u], 1);
        g_sorted[p] = v;
    }
}

// Fused: agg = adj@h1 (gather), conv1, pool logits, softmax -> g_hc, g_s
__global__ void k_gather1(const float* __restrict__ Wrel,
                          const float* __restrict__ brel,
                          const float* __restrict__ Wroot,
                          const float* __restrict__ Wpool,
                          const float* __restrict__ bpool) {
    __shared__ float Wr[H*H], Wo[H*H], Wp[H*K];
    __shared__ float br[H], bp[K];
    for (int i = threadIdx.x; i < H*H; i += blockDim.x) { Wr[i] = Wrel[i]; Wo[i] = Wroot[i]; }
    for (int i = threadIdx.x; i < H*K; i += blockDim.x) Wp[i] = Wpool[i];
    if (threadIdx.x < H) br[threadIdx.x] = brel[threadIdx.x];
    if (threadIdx.x < K) bp[threadIdx.x] = bpool[threadIdx.x];
    __syncthreads();

    int u = (blockIdx.x * blockDim.x + threadIdx.x) >> 5;
    int lane = threadIdx.x & 31;
    if (u >= NT) return;

    int d = g_deg[u];
    int start = g_cursor[u] - d;

    float a0 = 0.f, a1 = 0.f;
    int i = 0;
    for (; i + 1 < d; i += 2) {
        int d0 = g_sorted[start + i];
        int d1 = g_sorted[start + i + 1];
        a0 += g_h1[(size_t)d0*H + lane];
        a1 += g_h1[(size_t)d1*H + lane];
    }
    if (i < d) {
        int d0 = g_sorted[start + i];
        a0 += g_h1[(size_t)d0*H + lane];
    }
    float agg = a0 + a1;

    float h1v = g_h1[(size_t)u*H + lane];
    float acc = br[lane];
#pragma unroll
    for (int k = 0; k < H; k++) {
        float av = __shfl_sync(0xffffffffu, agg, k);
        float hv = __shfl_sync(0xffffffffu, h1v, k);
        acc += av * Wr[k*H + lane] + hv * Wo[k*H + lane];
    }
    g_hc[(size_t)u*H + lane] = acc;

    // pool logits (lanes 16-31 mirror lanes 0-15)
    int lk = lane & 15;
    float sl = bp[lk];
#pragma unroll
    for (int k = 0; k < H; k++) {
        float hv = __shfl_sync(0xffffffffu, acc, k);
        sl += hv * Wp[k*K + lk];
    }
    // softmax over 16 (within 16-lane groups)
    float m = sl;
#pragma unroll
    for (int o = 8; o >= 1; o >>= 1)
        m = fmaxf(m, __shfl_xor_sync(0xffffffffu, m, o, 16));
    float e = expf(sl - m);
    float sum = e;
#pragma unroll
    for (int o = 8; o >= 1; o >>= 1)
        sum += __shfl_xor_sync(0xffffffffu, sum, o, 16);
    float sv = e / sum;
    if (lane < 16) g_s[(size_t)u*K + lk] = sv;
}

// t[u] = sum over edges (u,v) of s[v]
__global__ void k_gather2() {
    int u = (blockIdx.x * blockDim.x + threadIdx.x) >> 5;
    int lane = threadIdx.x & 31;
    if (u >= NT) return;
    int lo = lane & 15;
    int half = lane >> 4;
    int d = g_deg[u];
    int start = g_cursor[u] - d;
    float t = 0.f;
    for (int i = half; i < d; i += 2) {
        int dd = g_sorted[start + i];
        t += g_s[(size_t)dd*K + lo];
    }
    t += __shfl_xor_sync(0xffffffffu, t, 16);
    if (lane < 16) g_t[(size_t)u*K + lo] = t;
}

// Per-graph: out_adj, ss, losses, normalize, conv2, readout, MLP, log_softmax
__global__ void k_graph(const float* __restrict__ Wrel2, const float* __restrict__ brel2,
                        const float* __restrict__ Wroot2,
                        const float* __restrict__ Wlin2, const float* __restrict__ blin2,
                        const float* __restrict__ Wlin3, const float* __restrict__ blin3,
                        float* __restrict__ out) {
    __shared__ float sS[N*K];     // 16 KB
    __shared__ float sT[N*K];     // 16 KB
    __shared__ float sAdj[K*K];
    __shared__ float sSS[K*K];
    __shared__ float sPx[K*H];
    __shared__ float sM1[K*H];
    __shared__ float sH2[K*H];
    __shared__ float sRed[256];
    __shared__ float sD[K];
    __shared__ float sR[H];
    __shared__ float sH3[H];
    __shared__ float sO[FOUT];

    int b = blockIdx.x, tid = threadIdx.x;
    size_t baseK = (size_t)b * N * K;
    for (int i = tid; i < N*K; i += 256) { sS[i] = g_s[baseK + i]; sT[i] = g_t[baseK + i]; }
    __syncthreads();

    int k = tid >> 4, j = tid & 15;
    float oa = 0.f, sv = 0.f;
    for (int n = 0; n < N; n++) {
        float a = sS[n*K + k];
        oa += a * sT[n*K + j];
        sv += a * sS[n*K + j];
    }
    sAdj[tid] = oa;
    sSS[tid] = sv;

    // mincut denominator: sum_n deg[n] * ||s[n]||^2
    float dv = (float)g_deg[b*N + tid];
    float l2 = 0.f;
#pragma unroll
    for (int kk = 0; kk < K; kk++) { float s = sS[tid*K + kk]; l2 += s*s; }
    sRed[tid] = dv * l2;
    __syncthreads();
    for (int off = 128; off > 0; off >>= 1) { if (tid < off) sRed[tid] += sRed[tid + off]; __syncthreads(); }
    float den = sRed[0];
    __syncthreads();
    if (tid == 0) {
        float num = 0.f;
        for (int kk = 0; kk < K; kk++) num += sAdj[kk*K + kk];
        g_loss[b] = -(num / den);
    }

    // ortho loss
    float ssv = sSS[tid];
    sRed[tid] = ssv * ssv;
    __syncthreads();
    for (int off = 128; off > 0; off >>= 1) { if (tid < off) sRed[tid] += sRed[tid + off]; __syncthreads(); }
    float nrm = sqrtf(sRed[0]);
    __syncthreads();
    float diff = ssv / nrm - ((k == j) ? 0.25f : 0.f);  // 1/sqrt(16) = 0.25
    sRed[tid] = diff * diff;
    __syncthreads();
    for (int off = 128; off > 0; off >>= 1) { if (tid < off) sRed[tid] += sRed[tid + off]; __syncthreads(); }
    if (tid == 0) g_loss[B + b] = sqrtf(sRed[0]);
    __syncthreads();

    // normalize out_adj: zero diag, symmetric sqrt-degree norm
    if (k == j) sAdj[tid] = 0.f;
    __syncthreads();
    if (tid < K) {
        float rs = 0.f;
        for (int jj = 0; jj < K; jj++) rs += sAdj[tid*K + jj];
        sD[tid] = sqrtf(rs) + EPSF;
    }
    __syncthreads();
    sAdj[tid] = sAdj[tid] / (sD[k] * sD[j]);
    __syncthreads();

    // pooled x: px[k][h] = sum_n s[n,k] * hc[n,h]
    {
        int h = tid & 31, kk0 = tid >> 5;
        const float* hcb = g_hc + (size_t)b * N * H + h;
#pragma unroll
        for (int rep = 0; rep < 2; rep++) {
            int kc = kk0 + rep*8;
            float p = 0.f;
            for (int n = 0; n < N; n++) p += sS[n*K + kc] * hcb[(size_t)n*H];
            sPx[kc*H + h] = p;
        }
    }
    __syncthreads();

    // conv2: m1 = adj_p @ px
    {
        int h = tid & 31, kk0 = tid >> 5;
#pragma unroll
        for (int rep = 0; rep < 2; rep++) {
            int kc = kk0 + rep*8;
            float m1 = 0.f;
#pragma unroll
            for (int jj = 0; jj < K; jj++) m1 += sAdj[kc*K + jj] * sPx[jj*H + h];
            sM1[kc*H + h] = m1;
        }
    }
    __syncthreads();
    {
        int h = tid & 31, kk0 = tid >> 5;
#pragma unroll
        for (int rep = 0; rep < 2; rep++) {
            int kc = kk0 + rep*8;
            float acc = brel2[h];
            for (int c = 0; c < H; c++)
                acc += sM1[kc*H + c] * Wrel2[c*H + h] + sPx[kc*H + c] * Wroot2[c*H + h];
            sH2[kc*H + h] = acc;
        }
    }
    __syncthreads();

    // readout over clusters
    if (tid < H) {
        float r = 0.f;
#pragma unroll
        for (int kk = 0; kk < K; kk++) r += sH2[kk*H + tid];
        sR[tid] = r;
    }
    __syncthreads();
    if (tid < H) {
        float a = blin2[tid];
        for (int c = 0; c < H; c++) a += sR[c] * Wlin2[c*H + tid];
        sH3[tid] = fmaxf(a, 0.f);
    }
    __syncthreads();
    if (tid < FOUT) {
        float a = blin3[tid];
        for (int c = 0; c < H; c++) a += sH3[c] * Wlin3[c*FOUT + tid];
        sO[tid] = a;
    }
    __syncthreads();
    if (tid == 0) {
        float m = sO[0];
        for (int i = 1; i < FOUT; i++) m = fmaxf(m, sO[i]);
        float s = 0.f;
        for (int i = 0; i < FOUT; i++) s += expf(sO[i] - m);
        float lse = m + logf(s);
        for (int i = 0; i < FOUT; i++) out[b*FOUT + i] = sO[i] - lse;
    }
}

__global__ void k_final(float* __restrict__ out, int out_size) {
    __shared__ float s1[B], s2[B];
    int t = threadIdx.x;
    s1[t] = g_loss[t];
    s2[t] = g_loss[B + t];
    __syncthreads();
    for (int off = 256; off > 0; off >>= 1) {
        if (t < off) { s1[t] += s1[t + off]; s2[t] += s2[t + off]; }
        __syncthreads();
    }
    if (t == 0) {
        if (out_size > B*FOUT)     out[B*FOUT]     = s1[0] / (float)B;
        if (out_size > B*FOUT + 1) out[B*FOUT + 1] = s2[0] / (float)B;
    }
}

// ---------------- launch ----------------
extern "C" void kernel_launch(void* const* d_in, const int* in_sizes, int n_in,
                              void* d_out, int out_size) {
    const float* x     = (const float*)d_in[0];
    const int*   ei    = (const int*)d_in[1];   // edge_index, int64 narrowed to int32 by harness
    // d_in[2] = batch (implied: node i belongs to graph i/N)
    const float* Wlin1 = (const float*)d_in[3];
    const float* blin1 = (const float*)d_in[4];
    const float* Wrel1 = (const float*)d_in[5];
    const float* brel1 = (const float*)d_in[6];
    const float* Wroot1= (const float*)d_in[7];
    const float* Wpool = (const float*)d_in[8];
    const float* bpool = (const float*)d_in[9];
    const float* Wrel2 = (const float*)d_in[10];
    const float* brel2 = (const float*)d_in[11];
    const float* Wroot2= (const float*)d_in[12];
    const float* Wlin2 = (const float*)d_in[13];
    const float* blin2 = (const float*)d_in[14];
    const float* Wlin3 = (const float*)d_in[15];
    const float* blin3 = (const float*)d_in[16];
    float* out = (float*)d_out;

    k_zero<<<NT/256, 256>>>();
    k_lin1<<<NT/8, 256>>>(x, Wlin1, blin1);
    k_count<<<ET/256, 256>>>(ei);
    k_scan<<<B, N>>>();
    k_scatter<<<ET/256, 256>>>(ei);
    k_gather1<<<NT/8, 256>>>(Wrel1, brel1, Wroot1, Wpool, bpool);
    k_gather2<<<NT/8, 256>>>();
    k_graph<<<B, 256>>>(Wrel2, brel2, Wroot2, Wlin2, blin2, Wlin3, blin3, out);
    k_final<<<1, B>>>(out, out_size);
}

// round 4
// speedup vs baseline: 1.3600x; 1.3600x over previous
#include <cuda_runtime.h>

#define B 512
#define N 256
#define E_PER 8192
#define NT (B*N)        // 131072 nodes
#define ET (B*E_PER)    // 4194304 edges
#define FIN 128
#define H 32
#define K 16
#define FOUT 10
#define EPSF 1e-15f
#define FULL 0xffffffffu

// ---------------- scratch (device globals; no allocation) ----------------
__device__ __align__(16) float g_h1[NT*H];     // lin1 output
__device__ __align__(16) float g_hc[NT*H];     // conv1 output
__device__ __align__(16) float g_s[NT*K];      // softmax cluster assignment
__device__ __align__(16) float g_t[NT*K];      // t = adj @ s
__device__ int   g_deg[NT];
__device__ int   g_start[NT];
__device__ int   g_sorted[ET];   // dst ids grouped by src (per-graph segments)
__device__ float g_loss[2*B];

// ---------------- fused count + scan + scatter (per-graph CTA, smem atomics) ----
__global__ void k_sort(const int* __restrict__ ei) {
    __shared__ int cnt[N];
    __shared__ int sc[N];
    int b = blockIdx.x, t = threadIdx.x;
    cnt[t] = 0;
    __syncthreads();
    const int* src = ei + b*E_PER;
    const int* dst = ei + ET + b*E_PER;
    int base = b*N;
    int sv[E_PER/256];
#pragma unroll
    for (int i = 0; i < E_PER/256; i++) {
        sv[i] = src[t + i*256] - base;
        atomicAdd(&cnt[sv[i]], 1);
    }
    __syncthreads();
    int d = cnt[t];
    sc[t] = d;
    __syncthreads();
    for (int off = 1; off < N; off <<= 1) {
        int v = (t >= off) ? sc[t - off] : 0;
        __syncthreads();
        sc[t] += v;
        __syncthreads();
    }
    int start = sc[t] - d;
    g_deg[base + t] = d;
    g_start[base + t] = b*E_PER + start;
    cnt[t] = start;
    __syncthreads();
    int* out = g_sorted + b*E_PER;
#pragma unroll
    for (int i = 0; i < E_PER/256; i++) {
        int p = atomicAdd(&cnt[sv[i]], 1);
        out[p] = dst[t + i*256];
    }
}

// ---------------- lin1: h1 = x @ W1 + b1, 4 rows per warp ----------------
__global__ void k_lin1(const float* __restrict__ x,
                       const float* __restrict__ W,
                       const float* __restrict__ b) {
    __shared__ float Ws[FIN*H];
    __shared__ float bs[H];
    for (int i = threadIdx.x; i < FIN*H; i += blockDim.x) Ws[i] = W[i];
    if (threadIdx.x < H) bs[threadIdx.x] = b[threadIdx.x];
    __syncthreads();
    int warp = (blockIdx.x * blockDim.x + threadIdx.x) >> 5;
    int lane = threadIdx.x & 31;
    int r0 = warp * 4;
    if (r0 >= NT) return;
    float xv[4][4];
#pragma unroll
    for (int r = 0; r < 4; r++) {
        const float* xr = x + (size_t)(r0 + r) * FIN;
#pragma unroll
        for (int i = 0; i < 4; i++) xv[r][i] = xr[i*32 + lane];
    }
    float acc[4];
#pragma unroll
    for (int r = 0; r < 4; r++) acc[r] = bs[lane];
#pragma unroll
    for (int k = 0; k < FIN; k++) {
        float w = Ws[k*H + lane];
#pragma unroll
        for (int r = 0; r < 4; r++) {
            float xk = __shfl_sync(FULL, xv[r][k >> 5], k & 31);
            acc[r] += xk * w;
        }
    }
#pragma unroll
    for (int r = 0; r < 4; r++) g_h1[(size_t)(r0 + r)*H + lane] = acc[r];
}

// -------- Fused: agg = adj@h1 (float4 gather), conv1, pool, softmax --------
__global__ void k_gather1(const float* __restrict__ Wrel,
                          const float* __restrict__ brel,
                          const float* __restrict__ Wroot,
                          const float* __restrict__ Wpool,
                          const float* __restrict__ bpool) {
    __shared__ float Wr[H*H], Wo[H*H], Wp[H*K];
    __shared__ float br[H], bp[K];
    for (int i = threadIdx.x; i < H*H; i += blockDim.x) { Wr[i] = Wrel[i]; Wo[i] = Wroot[i]; }
    for (int i = threadIdx.x; i < H*K; i += blockDim.x) Wp[i] = Wpool[i];
    if (threadIdx.x < H) br[threadIdx.x] = brel[threadIdx.x];
    if (threadIdx.x < K) bp[threadIdx.x] = bpool[threadIdx.x];
    __syncthreads();

    int u = (blockIdx.x * blockDim.x + threadIdx.x) >> 5;
    int lane = threadIdx.x & 31;
    if (u >= NT) return;

    int d = g_deg[u];
    int start = g_start[u];
    int grp = lane >> 3;   // neighbor slot 0..3
    int q   = lane & 7;    // which float4 of the 32-float row

    const float4* h1v4 = (const float4*)g_h1;
    const int* idx = g_sorted + start;
    float4 a = make_float4(0.f, 0.f, 0.f, 0.f);
    for (int i = grp; i < d; i += 4) {
        int v = idx[i];
        float4 r = h1v4[(size_t)v*8 + q];
        a.x += r.x; a.y += r.y; a.z += r.z; a.w += r.w;
    }
    // reduce across the 4 neighbor groups (lane bits 3,4)
    a.x += __shfl_xor_sync(FULL, a.x, 8);  a.x += __shfl_xor_sync(FULL, a.x, 16);
    a.y += __shfl_xor_sync(FULL, a.y, 8);  a.y += __shfl_xor_sync(FULL, a.y, 16);
    a.z += __shfl_xor_sync(FULL, a.z, 8);  a.z += __shfl_xor_sync(FULL, a.z, 16);
    a.w += __shfl_xor_sync(FULL, a.w, 8);  a.w += __shfl_xor_sync(FULL, a.w, 16);
    // now lane l holds agg channels 4*(l&7)..4*(l&7)+3 (replicated over groups)

    float4 hq = h1v4[(size_t)u*8 + q];   // own row quad (broadcast across groups)

    float o = br[lane];
#pragma unroll
    for (int c = 0; c < 8; c++) {
        float ax = __shfl_sync(FULL, a.x, c);
        float ay = __shfl_sync(FULL, a.y, c);
        float az = __shfl_sync(FULL, a.z, c);
        float aw = __shfl_sync(FULL, a.w, c);
        float hx = __shfl_sync(FULL, hq.x, c);
        float hy = __shfl_sync(FULL, hq.y, c);
        float hz = __shfl_sync(FULL, hq.z, c);
        float hw = __shfl_sync(FULL, hq.w, c);
        o += ax*Wr[(4*c+0)*H + lane] + hx*Wo[(4*c+0)*H + lane];
        o += ay*Wr[(4*c+1)*H + lane] + hy*Wo[(4*c+1)*H + lane];
        o += az*Wr[(4*c+2)*H + lane] + hz*Wo[(4*c+2)*H + lane];
        o += aw*Wr[(4*c+3)*H + lane] + hw*Wo[(4*c+3)*H + lane];
    }
    g_hc[(size_t)u*H + lane] = o;

    // pool logits (lanes 16-31 mirror lanes 0-15)
    int lk = lane & 15;
    float sl = bp[lk];
#pragma unroll
    for (int k = 0; k < H; k++) {
        float hv = __shfl_sync(FULL, o, k);
        sl += hv * Wp[k*K + lk];
    }
    float m = sl;
#pragma unroll
    for (int off = 8; off >= 1; off >>= 1)
        m = fmaxf(m, __shfl_xor_sync(FULL, m, off, 16));
    float e = expf(sl - m);
    float sum = e;
#pragma unroll
    for (int off = 8; off >= 1; off >>= 1)
        sum += __shfl_xor_sync(FULL, sum, off, 16);
    float svv = e / sum;
    if (lane < 16) g_s[(size_t)u*K + lk] = svv;
}

// t[u] = sum over edges (u,v) of s[v] ; float4, 8 neighbors per warp-instr
__global__ void k_gather2() {
    int u = (blockIdx.x * blockDim.x + threadIdx.x) >> 5;
    int lane = threadIdx.x & 31;
    if (u >= NT) return;
    int grp = lane >> 2;   // neighbor slot 0..7
    int q   = lane & 3;    // which float4 of the 16-float row
    int d = g_deg[u];
    int start = g_start[u];
    const float4* s4 = (const float4*)g_s;
    const int* idx = g_sorted + start;
    float4 a = make_float4(0.f, 0.f, 0.f, 0.f);
    for (int i = grp; i < d; i += 8) {
        int v = idx[i];
        float4 r = s4[(size_t)v*4 + q];
        a.x += r.x; a.y += r.y; a.z += r.z; a.w += r.w;
    }
    a.x += __shfl_xor_sync(FULL, a.x, 4); a.x += __shfl_xor_sync(FULL, a.x, 8); a.x += __shfl_xor_sync(FULL, a.x, 16);
    a.y += __shfl_xor_sync(FULL, a.y, 4); a.y += __shfl_xor_sync(FULL, a.y, 8); a.y += __shfl_xor_sync(FULL, a.y, 16);
    a.z += __shfl_xor_sync(FULL, a.z, 4); a.z += __shfl_xor_sync(FULL, a.z, 8); a.z += __shfl_xor_sync(FULL, a.z, 16);
    a.w += __shfl_xor_sync(FULL, a.w, 4); a.w += __shfl_xor_sync(FULL, a.w, 8); a.w += __shfl_xor_sync(FULL, a.w, 16);
    if (lane < 4) ((float4*)g_t)[(size_t)u*4 + lane] = a;
}

// Per-graph: out_adj, ss, losses, normalize, conv2, readout, MLP, log_softmax
__global__ void k_graph(const float* __restrict__ Wrel2, const float* __restrict__ brel2,
                        const float* __restrict__ Wroot2,
                        const float* __restrict__ Wlin2, const float* __restrict__ blin2,
                        const float* __restrict__ Wlin3, const float* __restrict__ blin3,
                        float* __restrict__ out) {
    __shared__ float sS[N*K];     // 16 KB
    __shared__ float sT[N*K];     // 16 KB
    __shared__ float sAdj[K*K];
    __shared__ float sSS[K*K];
    __shared__ float sPx[K*H];
    __shared__ float sM1[K*H];
    __shared__ float sH2[K*H];
    __shared__ float sRed[256];
    __shared__ float sD[K];
    __shared__ float sR[H];
    __shared__ float sH3[H];
    __shared__ float sO[FOUT];

    int b = blockIdx.x, tid = threadIdx.x;
    size_t baseK4 = (size_t)b * N * 4;   // in float4 units (N*K/4 = N*4)
    const float4* gs4 = (const float4*)g_s;
    const float4* gt4 = (const float4*)g_t;
    for (int i = tid; i < N*4; i += 256) {
        ((float4*)sS)[i] = gs4[baseK4 + i];
        ((float4*)sT)[i] = gt4[baseK4 + i];
    }
    __syncthreads();

    int k = tid >> 4, j = tid & 15;
    float oa = 0.f, sv = 0.f;
    for (int n = 0; n < N; n++) {
        float a = sS[n*K + k];
        oa += a * sT[n*K + j];
        sv += a * sS[n*K + j];
    }
    sAdj[tid] = oa;
    sSS[tid] = sv;

    // mincut denominator: sum_n deg[n] * ||s[n]||^2
    float dv = (float)g_deg[b*N + tid];
    float l2 = 0.f;
#pragma unroll
    for (int kk = 0; kk < K; kk++) { float s = sS[tid*K + kk]; l2 += s*s; }
    sRed[tid] = dv * l2;
    __syncthreads();
    for (int off = 128; off > 0; off >>= 1) { if (tid < off) sRed[tid] += sRed[tid + off]; __syncthreads(); }
    float den = sRed[0];
    __syncthreads();
    if (tid == 0) {
        float num = 0.f;
        for (int kk = 0; kk < K; kk++) num += sAdj[kk*K + kk];
        g_loss[b] = -(num / den);
    }

    // ortho loss
    float ssv = sSS[tid];
    sRed[tid] = ssv * ssv;
    __syncthreads();
    for (int off = 128; off > 0; off >>= 1) { if (tid < off) sRed[tid] += sRed[tid + off]; __syncthreads(); }
    float nrm = sqrtf(sRed[0]);
    __syncthreads();
    float diff = ssv / nrm - ((k == j) ? 0.25f : 0.f);  // 1/sqrt(16) = 0.25
    sRed[tid] = diff * diff;
    __syncthreads();
    for (int off = 128; off > 0; off >>= 1) { if (tid < off) sRed[tid] += sRed[tid + off]; __syncthreads(); }
    if (tid == 0) g_loss[B + b] = sqrtf(sRed[0]);
    __syncthreads();

    // normalize out_adj: zero diag, symmetric sqrt-degree norm
    if (k == j) sAdj[tid] = 0.f;
    __syncthreads();
    if (tid < K) {
        float rs = 0.f;
        for (int jj = 0; jj < K; jj++) rs += sAdj[tid*K + jj];
        sD[tid] = sqrtf(rs) + EPSF;
    }
    __syncthreads();
    sAdj[tid] = sAdj[tid] / (sD[k] * sD[j]);
    __syncthreads();

    // pooled x: px[k][h] = sum_n s[n,k] * hc[n,h]
    {
        int h = tid & 31, kk0 = tid >> 5;
        const float* hcb = g_hc + (size_t)b * N * H + h;
#pragma unroll
        for (int rep = 0; rep < 2; rep++) {
            int kc = kk0 + rep*8;
            float p = 0.f;
            for (int n = 0; n < N; n++) p += sS[n*K + kc] * hcb[(size_t)n*H];
            sPx[kc*H + h] = p;
        }
    }
    __syncthreads();

    // conv2: m1 = adj_p @ px
    {
        int h = tid & 31, kk0 = tid >> 5;
#pragma unroll
        for (int rep = 0; rep < 2; rep++) {
            int kc = kk0 + rep*8;
            float m1 = 0.f;
#pragma unroll
            for (int jj = 0; jj < K; jj++) m1 += sAdj[kc*K + jj] * sPx[jj*H + h];
            sM1[kc*H + h] = m1;
        }
    }
    __syncthreads();
    {
        int h = tid & 31, kk0 = tid >> 5;
#pragma unroll
        for (int rep = 0; rep < 2; rep++) {
            int kc = kk0 + rep*8;
            float acc = brel2[h];
            for (int c = 0; c < H; c++)
                acc += sM1[kc*H + c] * Wrel2[c*H + h] + sPx[kc*H + c] * Wroot2[c*H + h];
            sH2[kc*H + h] = acc;
        }
    }
    __syncthreads();

    // readout over clusters
    if (tid < H) {
        float r = 0.f;
#pragma unroll
        for (int kk = 0; kk < K; kk++) r += sH2[kk*H + tid];
        sR[tid] = r;
    }
    __syncthreads();
    if (tid < H) {
        float a = blin2[tid];
        for (int c = 0; c < H; c++) a += sR[c] * Wlin2[c*H + tid];
        sH3[tid] = fmaxf(a, 0.f);
    }
    __syncthreads();
    if (tid < FOUT) {
        float a = blin3[tid];
        for (int c = 0; c < H; c++) a += sH3[c] * Wlin3[c*FOUT + tid];
        sO[tid] = a;
    }
    __syncthreads();
    if (tid == 0) {
        float m = sO[0];
        for (int i = 1; i < FOUT; i++) m = fmaxf(m, sO[i]);
        float s = 0.f;
        for (int i = 0; i < FOUT; i++) s += expf(sO[i] - m);
        float lse = m + logf(s);
        for (int i = 0; i < FOUT; i++) out[b*FOUT + i] = sO[i] - lse;
    }
}

__global__ void k_final(float* __restrict__ out, int out_size) {
    __shared__ float s1[B], s2[B];
    int t = threadIdx.x;
    s1[t] = g_loss[t];
    s2[t] = g_loss[B + t];
    __syncthreads();
    for (int off = 256; off > 0; off >>= 1) {
        if (t < off) { s1[t] += s1[t + off]; s2[t] += s2[t + off]; }
        __syncthreads();
    }
    if (t == 0) {
        if (out_size > B*FOUT)     out[B*FOUT]     = s1[0] / (float)B;
        if (out_size > B*FOUT + 1) out[B*FOUT + 1] = s2[0] / (float)B;
    }
}

// ---------------- launch ----------------
extern "C" void kernel_launch(void* const* d_in, const int* in_sizes, int n_in,
                              void* d_out, int out_size) {
    const float* x     = (const float*)d_in[0];
    const int*   ei    = (const int*)d_in[1];   // edge_index (int64 narrowed to int32)
    // d_in[2] = batch (implied: node i belongs to graph i/N)
    const float* Wlin1 = (const float*)d_in[3];
    const float* blin1 = (const float*)d_in[4];
    const float* Wrel1 = (const float*)d_in[5];
    const float* brel1 = (const float*)d_in[6];
    const float* Wroot1= (const float*)d_in[7];
    const float* Wpool = (const float*)d_in[8];
    const float* bpool = (const float*)d_in[9];
    const float* Wrel2 = (const float*)d_in[10];
    const float* brel2 = (const float*)d_in[11];
    const float* Wroot2= (const float*)d_in[12];
    const float* Wlin2 = (const float*)d_in[13];
    const float* blin2 = (const float*)d_in[14];
    const float* Wlin3 = (const float*)d_in[15];
    const float* blin3 = (const float*)d_in[16];
    float* out = (float*)d_out;

    k_sort<<<B, N>>>(ei);
    k_lin1<<<NT/32, 256>>>(x, Wlin1, blin1);
    k_gather1<<<NT/8, 256>>>(Wrel1, brel1, Wroot1, Wpool, bpool);
    k_gather2<<<NT/8, 256>>>();
    k_graph<<<B, 256>>>(Wrel2, brel2, Wroot2, Wlin2, blin2, Wlin3, blin3, out);
    k_final<<<1, B>>>(out, out_size);
}

// round 5
// speedup vs baseline: 1.5594x; 1.1466x over previous
#include <cuda_runtime.h>

#define B 512
#define N 256
#define E_PER 8192
#define NT (B*N)        // 131072 nodes
#define ET (B*E_PER)    // 4194304 edges
#define FIN 128
#define H 32
#define K 16
#define FOUT 10
#define EPSF 1e-15f
#define FULL 0xffffffffu
#define WSTR 36         // padded transposed-weight stride (conflict-free LDS.128)

// ---------------- globals ----------------
__device__ __align__(16) float g_h1[NT*H];   // lin1 output
__device__ float g_loss[2*B];

// ---------------- mega-kernel shared layout ----------------
struct SMem {
    float h1[N*H];            // 32768 B  (staged h1 for this graph)
    float s[N*K];             // 16384 B  (softmax assignments)
    float buf[2048];          // 8192  B  (reduction scratch / m1 / h2)
    float wr[H*WSTR];         // 4608  B  (Wrel transposed  [lane][k])
    float wo[H*WSTR];         // 4608  B  (Wroot transposed)
    float wp[K*WSTR];         // 2304  B  (Wpool transposed [lk][k])
    float br[H];
    float bp[K];
    float px[K*H];            // pooled features s^T hc
    float adj[K*K];
    float ssm[K*K];
    float red[32];            // per-warp den partials
    float tbuf[8*16];         // per-warp t scratch
    float sd[K];
    float sr[H];
    float sh3[H];
    float so[FOUT];
    unsigned short idx[E_PER];// sorted local dst ids (16384 B)
    int deg[N];
    int start[N];
    int cnt[N];
};

// ---------------- lin1: h1 = x @ W1 + b1, 4 rows per warp (proven) ----------------
__global__ void k_lin1(const float* __restrict__ x,
                       const float* __restrict__ W,
                       const float* __restrict__ b) {
    __shared__ float Ws[FIN*H];
    __shared__ float bs[H];
    for (int i = threadIdx.x; i < FIN*H; i += blockDim.x) Ws[i] = W[i];
    if (threadIdx.x < H) bs[threadIdx.x] = b[threadIdx.x];
    __syncthreads();
    int warp = (blockIdx.x * blockDim.x + threadIdx.x) >> 5;
    int lane = threadIdx.x & 31;
    int r0 = warp * 4;
    if (r0 >= NT) return;
    float xv[4][4];
#pragma unroll
    for (int r = 0; r < 4; r++) {
        const float* xr = x + (size_t)(r0 + r) * FIN;
#pragma unroll
        for (int i = 0; i < 4; i++) xv[r][i] = xr[i*32 + lane];
    }
    float acc[4];
#pragma unroll
    for (int r = 0; r < 4; r++) acc[r] = bs[lane];
#pragma unroll
    for (int k = 0; k < FIN; k++) {
        float w = Ws[k*H + lane];
#pragma unroll
        for (int r = 0; r < 4; r++) {
            float xk = __shfl_sync(FULL, xv[r][k >> 5], k & 31);
            acc[r] += xk * w;
        }
    }
#pragma unroll
    for (int r = 0; r < 4; r++) g_h1[(size_t)(r0 + r)*H + lane] = acc[r];
}

// ---------------- mega: everything after lin1, one CTA per graph ----------------
__global__ __launch_bounds__(256, 2)
void k_mega(const int* __restrict__ ei,
            const float* __restrict__ Wrel,  const float* __restrict__ brel,
            const float* __restrict__ Wroot, const float* __restrict__ Wpool,
            const float* __restrict__ bpool,
            const float* __restrict__ Wrel2, const float* __restrict__ brel2,
            const float* __restrict__ Wroot2,
            const float* __restrict__ Wlin2, const float* __restrict__ blin2,
            const float* __restrict__ Wlin3, const float* __restrict__ blin3,
            float* __restrict__ out)
{
    extern __shared__ char smraw[];
    SMem* sm = (SMem*)smraw;
    int b = blockIdx.x, tid = threadIdx.x;
    int w = tid >> 5, lane = tid & 31;
    int base = b * N;

    // ---- stage h1 + weights (transposed, padded) ----
    {
        const float4* gh4 = ((const float4*)g_h1) + (size_t)b*N*8;
        float4* sh4 = (float4*)sm->h1;
        for (int i = tid; i < N*8; i += 256) sh4[i] = gh4[i];
    }
    for (int i = tid; i < H*H; i += 256) {
        int k = i >> 5, l = i & 31;
        sm->wr[l*WSTR + k] = Wrel[i];
        sm->wo[l*WSTR + k] = Wroot[i];
    }
    for (int i = tid; i < H*K; i += 256) {
        int k = i >> 4, l = i & 15;
        sm->wp[l*WSTR + k] = Wpool[i];
    }
    if (tid < H) sm->br[tid] = brel[tid];
    if (tid < K) sm->bp[tid] = bpool[tid];
    sm->cnt[tid] = 0;
    __syncthreads();

    // ---- sort edges by src (count / scan / scatter), smem only ----
    const int* src = ei + b*E_PER;
    const int* dst = ei + ET + b*E_PER;
#pragma unroll
    for (int i = 0; i < E_PER/256; i++)
        atomicAdd(&sm->cnt[src[tid + i*256] - base], 1);
    __syncthreads();
    int d0 = sm->cnt[tid];
    sm->start[tid] = d0;
    __syncthreads();
    for (int off = 1; off < N; off <<= 1) {
        int v = (tid >= off) ? sm->start[tid - off] : 0;
        __syncthreads();
        sm->start[tid] += v;
        __syncthreads();
    }
    int st0 = sm->start[tid] - d0;
    sm->deg[tid] = d0;
    sm->start[tid] = st0;
    sm->cnt[tid] = st0;
    __syncthreads();
#pragma unroll
    for (int i = 0; i < E_PER/256; i++) {
        int u = src[tid + i*256] - base;
        int p = atomicAdd(&sm->cnt[u], 1);
        sm->idx[p] = (unsigned short)(dst[tid + i*256] - base);
    }
    __syncthreads();

    // ---- Phase A: per node (warp): gather agg, conv1, pool, softmax, px rank-1 ----
    float px_reg[16];
#pragma unroll
    for (int k = 0; k < 16; k++) px_reg[k] = 0.f;

    {
        int grp = lane >> 3, q8 = lane & 7;
        const float4* h1r = (const float4*)sm->h1;
        for (int u = w*32; u < w*32 + 32; u++) {
            int d  = sm->deg[u];
            int st = sm->start[u];
            float4 a = make_float4(0.f, 0.f, 0.f, 0.f);
            for (int i = grp; i < d; i += 4) {
                int v = sm->idx[st + i];
                float4 r = h1r[v*8 + q8];
                a.x += r.x; a.y += r.y; a.z += r.z; a.w += r.w;
            }
            a.x += __shfl_xor_sync(FULL, a.x, 8); a.x += __shfl_xor_sync(FULL, a.x, 16);
            a.y += __shfl_xor_sync(FULL, a.y, 8); a.y += __shfl_xor_sync(FULL, a.y, 16);
            a.z += __shfl_xor_sync(FULL, a.z, 8); a.z += __shfl_xor_sync(FULL, a.z, 16);
            a.w += __shfl_xor_sync(FULL, a.w, 8); a.w += __shfl_xor_sync(FULL, a.w, 16);

            float4 hq = h1r[u*8 + q8];

            float o = sm->br[lane];
#pragma unroll
            for (int c = 0; c < 8; c++) {
                float4 wrv = *(const float4*)&sm->wr[lane*WSTR + 4*c];
                float4 wov = *(const float4*)&sm->wo[lane*WSTR + 4*c];
                float ax = __shfl_sync(FULL, a.x, c), ay = __shfl_sync(FULL, a.y, c);
                float az = __shfl_sync(FULL, a.z, c), aw = __shfl_sync(FULL, a.w, c);
                float hx = __shfl_sync(FULL, hq.x, c), hy = __shfl_sync(FULL, hq.y, c);
                float hz = __shfl_sync(FULL, hq.z, c), hw = __shfl_sync(FULL, hq.w, c);
                o += ax*wrv.x + hx*wov.x;
                o += ay*wrv.y + hy*wov.y;
                o += az*wrv.z + hz*wov.z;
                o += aw*wrv.w + hw*wov.w;
            }

            // pool logits + softmax over K=16
            int lk = lane & 15;
            float sl = sm->bp[lk];
#pragma unroll
            for (int c = 0; c < 8; c++) {
                float4 wpv = *(const float4*)&sm->wp[lk*WSTR + 4*c];
                float h0 = __shfl_sync(FULL, o, 4*c+0);
                float h1v = __shfl_sync(FULL, o, 4*c+1);
                float h2v = __shfl_sync(FULL, o, 4*c+2);
                float h3v = __shfl_sync(FULL, o, 4*c+3);
                sl += h0*wpv.x + h1v*wpv.y + h2v*wpv.z + h3v*wpv.w;
            }
            float m = sl;
#pragma unroll
            for (int off = 8; off >= 1; off >>= 1)
                m = fmaxf(m, __shfl_xor_sync(FULL, m, off, 16));
            float e = expf(sl - m);
            float sum = e;
#pragma unroll
            for (int off = 8; off >= 1; off >>= 1)
                sum += __shfl_xor_sync(FULL, sum, off, 16);
            float sv = e / sum;
            if (lane < 16) sm->s[u*16 + lk] = sv;

            // px[k][h] += s[u,k] * hc[u,h]  (lane = h)
#pragma unroll
            for (int k = 0; k < 16; k++) {
                float sk = __shfl_sync(FULL, sv, k);
                px_reg[k] += sk * o;
            }
        }
    }
    __syncthreads();

    // ---- px reduction across 8 warps (two rounds of 4 via 8KB buf) ----
    for (int round = 0; round < 2; round++) {
        if ((w >> 2) == round) {
            int wl = w & 3;
#pragma unroll
            for (int k = 0; k < 16; k++)
                sm->buf[wl*512 + k*32 + lane] = px_reg[k];
        }
        __syncthreads();
        for (int i = tid; i < 512; i += 256) {
            float v = sm->buf[i] + sm->buf[512+i] + sm->buf[1024+i] + sm->buf[1536+i];
            if (round == 0) sm->px[i] = v; else sm->px[i] += v;
        }
        __syncthreads();
    }

    // ---- Phase B: t = A@s gather; accumulate out_adj = s^T t, ss = s^T s, den ----
    float oa[8], ob[8];
#pragma unroll
    for (int i = 0; i < 8; i++) { oa[i] = 0.f; ob[i] = 0.f; }
    float den_acc = 0.f;
    {
        int grp8 = lane >> 2, q4 = lane & 3;
        int j = lane & 15, kh = lane >> 4;
        const float4* ssr = (const float4*)sm->s;
        for (int u = w*32; u < w*32 + 32; u++) {
            int d  = sm->deg[u];
            int st = sm->start[u];
            float4 a = make_float4(0.f, 0.f, 0.f, 0.f);
            for (int i = grp8; i < d; i += 8) {
                int v = sm->idx[st + i];
                float4 r = ssr[v*4 + q4];
                a.x += r.x; a.y += r.y; a.z += r.z; a.w += r.w;
            }
            a.x += __shfl_xor_sync(FULL, a.x, 4); a.x += __shfl_xor_sync(FULL, a.x, 8); a.x += __shfl_xor_sync(FULL, a.x, 16);
            a.y += __shfl_xor_sync(FULL, a.y, 4); a.y += __shfl_xor_sync(FULL, a.y, 8); a.y += __shfl_xor_sync(FULL, a.y, 16);
            a.z += __shfl_xor_sync(FULL, a.z, 4); a.z += __shfl_xor_sync(FULL, a.z, 8); a.z += __shfl_xor_sync(FULL, a.z, 16);
            a.w += __shfl_xor_sync(FULL, a.w, 4); a.w += __shfl_xor_sync(FULL, a.w, 8); a.w += __shfl_xor_sync(FULL, a.w, 16);
            if (lane < 4) *(float4*)&sm->tbuf[w*16 + lane*4] = a;
            __syncwarp();
            float tj = sm->tbuf[w*16 + j];
            float sj = sm->s[u*16 + j];
            __syncwarp();   // protect tbuf before next iteration's store

            float v2 = sj*sj;
            v2 += __shfl_xor_sync(FULL, v2, 1, 16);
            v2 += __shfl_xor_sync(FULL, v2, 2, 16);
            v2 += __shfl_xor_sync(FULL, v2, 4, 16);
            v2 += __shfl_xor_sync(FULL, v2, 8, 16);
            den_acc += (float)d * v2;

#pragma unroll
            for (int kk = 0; kk < 8; kk++) {
                float su = sm->s[u*16 + kh*8 + kk];
                oa[kk] += su * tj;
                ob[kk] += su * sj;
            }
        }
    }
    __syncthreads();

    // ---- reduce out_adj, ss, den across warps ----
    {
        int j = lane & 15, kh = lane >> 4;
#pragma unroll
        for (int kk = 0; kk < 8; kk++)
            sm->buf[w*256 + (kh*8+kk)*16 + j] = oa[kk];
        if (lane == 0) sm->red[w] = den_acc;
        __syncthreads();
        float v = 0.f;
#pragma unroll
        for (int ww = 0; ww < 8; ww++) v += sm->buf[ww*256 + tid];
        sm->adj[tid] = v;
        __syncthreads();
#pragma unroll
        for (int kk = 0; kk < 8; kk++)
            sm->buf[w*256 + (kh*8+kk)*16 + j] = ob[kk];
        __syncthreads();
        float v2 = 0.f;
#pragma unroll
        for (int ww = 0; ww < 8; ww++) v2 += sm->buf[ww*256 + tid];
        sm->ssm[tid] = v2;
        __syncthreads();
    }

    // ---- losses ----
    int kq = tid >> 4, jq = tid & 15;
    if (tid == 0) {
        float den = 0.f;
        for (int i = 0; i < 8; i++) den += sm->red[i];
        float num = 0.f;
        for (int kk = 0; kk < K; kk++) num += sm->adj[kk*K + kk];
        g_loss[b] = -(num / den);
    }
    float ssv = sm->ssm[tid];
    sm->buf[tid] = ssv * ssv;
    __syncthreads();
    for (int off = 128; off > 0; off >>= 1) { if (tid < off) sm->buf[tid] += sm->buf[tid + off]; __syncthreads(); }
    float nrm = sqrtf(sm->buf[0]);
    __syncthreads();
    float diff = ssv / nrm - ((kq == jq) ? 0.25f : 0.f);   // 1/sqrt(16)
    sm->buf[tid] = diff * diff;
    __syncthreads();
    for (int off = 128; off > 0; off >>= 1) { if (tid < off) sm->buf[tid] += sm->buf[tid + off]; __syncthreads(); }
    if (tid == 0) g_loss[B + b] = sqrtf(sm->buf[0]);
    __syncthreads();

    // ---- normalize out_adj ----
    {
        float av = (kq == jq) ? 0.f : sm->adj[tid];
        sm->adj[tid] = av;
    }
    __syncthreads();
    if (tid < K) {
        float rs = 0.f;
        for (int jj = 0; jj < K; jj++) rs += sm->adj[tid*K + jj];
        sm->sd[tid] = sqrtf(rs) + EPSF;
    }
    __syncthreads();
    sm->adj[tid] = sm->adj[tid] / (sm->sd[kq] * sm->sd[jq]);
    __syncthreads();

    // ---- conv2 on pooled features (m1 -> buf[0:512], h2 -> buf[512:1024]) ----
    {
        int h = tid & 31, kk0 = tid >> 5;
#pragma unroll
        for (int rep = 0; rep < 2; rep++) {
            int kc = kk0 + rep*8;
            float m1 = 0.f;
#pragma unroll
            for (int jj = 0; jj < K; jj++) m1 += sm->adj[kc*K + jj] * sm->px[jj*H + h];
            sm->buf[kc*H + h] = m1;
        }
    }
    __syncthreads();
    {
        int h = tid & 31, kk0 = tid >> 5;
#pragma unroll
        for (int rep = 0; rep < 2; rep++) {
            int kc = kk0 + rep*8;
            float acc = brel2[h];
            for (int c = 0; c < H; c++)
                acc += sm->buf[kc*H + c] * Wrel2[c*H + h] + sm->px[kc*H + c] * Wroot2[c*H + h];
            sm->buf[512 + kc*H + h] = acc;
        }
    }
    __syncthreads();

    // ---- readout + MLP + log_softmax ----
    if (tid < H) {
        float r = 0.f;
#pragma unroll
        for (int kk = 0; kk < K; kk++) r += sm->buf[512 + kk*H + tid];
        sm->sr[tid] = r;
    }
    __syncthreads();
    if (tid < H) {
        float a2 = blin2[tid];
        for (int c = 0; c < H; c++) a2 += sm->sr[c] * Wlin2[c*H + tid];
        sm->sh3[tid] = fmaxf(a2, 0.f);
    }
    __syncthreads();
    if (tid < FOUT) {
        float a3 = blin3[tid];
        for (int c = 0; c < H; c++) a3 += sm->sh3[c] * Wlin3[c*FOUT + tid];
        sm->so[tid] = a3;
    }
    __syncthreads();
    if (tid == 0) {
        float m = sm->so[0];
        for (int i = 1; i < FOUT; i++) m = fmaxf(m, sm->so[i]);
        float s = 0.f;
        for (int i = 0; i < FOUT; i++) s += expf(sm->so[i] - m);
        float lse = m + logf(s);
        for (int i = 0; i < FOUT; i++) out[b*FOUT + i] = sm->so[i] - lse;
    }
}

__global__ void k_final(float* __restrict__ out, int out_size) {
    __shared__ float s1[B], s2[B];
    int t = threadIdx.x;
    s1[t] = g_loss[t];
    s2[t] = g_loss[B + t];
    __syncthreads();
    for (int off = 256; off > 0; off >>= 1) {
        if (t < off) { s1[t] += s1[t + off]; s2[t] += s2[t + off]; }
        __syncthreads();
    }
    if (t == 0) {
        if (out_size > B*FOUT)     out[B*FOUT]     = s1[0] / (float)B;
        if (out_size > B*FOUT + 1) out[B*FOUT + 1] = s2[0] / (float)B;
    }
}

// ---------------- launch ----------------
extern "C" void kernel_launch(void* const* d_in, const int* in_sizes, int n_in,
                              void* d_out, int out_size) {
    const float* x     = (const float*)d_in[0];
    const int*   ei    = (const int*)d_in[1];   // edge_index (int64 narrowed to int32)
    const float* Wlin1 = (const float*)d_in[3];
    const float* blin1 = (const float*)d_in[4];
    const float* Wrel1 = (const float*)d_in[5];
    const float* brel1 = (const float*)d_in[6];
    const float* Wroot1= (const float*)d_in[7];
    const float* Wpool = (const float*)d_in[8];
    const float* bpool = (const float*)d_in[9];
    const float* Wrel2 = (const float*)d_in[10];
    const float* brel2 = (const float*)d_in[11];
    const float* Wroot2= (const float*)d_in[12];
    const float* Wlin2 = (const float*)d_in[13];
    const float* blin2 = (const float*)d_in[14];
    const float* Wlin3 = (const float*)d_in[15];
    const float* blin3 = (const float*)d_in[16];
    float* out = (float*)d_out;

    cudaFuncSetAttribute(k_mega, cudaFuncAttributeMaxDynamicSharedMemorySize,
                         (int)sizeof(SMem));

    k_lin1<<<NT/32, 256>>>(x, Wlin1, blin1);
    k_mega<<<B, 256, sizeof(SMem)>>>(ei, Wrel1, brel1, Wroot1, Wpool, bpool,
                                     Wrel2, brel2, Wroot2,
                                     Wlin2, blin2, Wlin3, blin3, out);
    k_final<<<1, B>>>(out, out_size);
}

// round 6
// speedup vs baseline: 1.9806x; 1.2701x over previous
#include <cuda_runtime.h>

#define B 512
#define N 256
#define E_PER 8192
#define NT (B*N)        // 131072 nodes
#define ET (B*E_PER)    // 4194304 edges
#define FIN 128
#define H 32
#define K 16
#define FOUT 10
#define EPSF 1e-15f
#define FULL 0xffffffffu
#define WSTR 36         // padded transposed-weight stride (conflict-free LDS.128)
#define RS   260        // xs transpose stride (16B-aligned rows, low-conflict)

// ---------------- globals ----------------
__device__ __align__(16) float g_h1[NT*H];   // lin1 output
__device__ float g_loss[2*B];

// ---------------- f32x2 helpers ----------------
__device__ __forceinline__ unsigned long long pk2(float lo, float hi) {
    unsigned long long r;
    asm("mov.b64 %0, {%1,%2};" : "=l"(r)
        : "r"(__float_as_uint(lo)), "r"(__float_as_uint(hi)));
    return r;
}
__device__ __forceinline__ void fma2(unsigned long long& d,
                                     unsigned long long a, unsigned long long b) {
    asm("fma.rn.f32x2 %0, %1, %2, %0;" : "+l"(d) : "l"(a), "l"(b));
}
__device__ __forceinline__ void upk2(float& lo, float& hi, unsigned long long v) {
    unsigned int a, b2;
    asm("mov.b64 {%0,%1}, %2;" : "=r"(a), "=r"(b2) : "l"(v));
    lo = __uint_as_float(a); hi = __uint_as_float(b2);
}

// ---------------- lin1: h1 = x @ W1 + b1 (register-tiled, FFMA2) ----------------
__global__ __launch_bounds__(256)
void k_lin1(const float* __restrict__ x,
            const float* __restrict__ W,
            const float* __restrict__ b) {
    __shared__ float ws[FIN*H];   // W[k][c], 16 KB
    __shared__ float xs[16*RS];   // transposed x tile: xs[k][row]
    __shared__ float bs[H];
    int tid = threadIdx.x;
    for (int i = tid; i < FIN*H; i += 256) ws[i] = W[i];
    if (tid < H) bs[tid] = b[tid];

    int row0 = blockIdx.x * 256;
    int c0 = (tid & 7) * 4;       // 4 output cols
    int r0 = (tid >> 3) * 8;      // 8 output rows

    int lr = tid >> 2;            // staging row (pass 0), passes add 64
    int q  = tid & 3;             // staging k-quad

    // prefetch k-tile 0
    float4 nx[4];
#pragma unroll
    for (int p = 0; p < 4; p++)
        nx[p] = *(const float4*)&x[(size_t)(row0 + lr + p*64)*FIN + q*4];

    __syncthreads();

    // accumulators: acc[pr][c] = packed (row r0+2pr, row r0+2pr+1) at col c0+c
    unsigned long long acc[4][4];
#pragma unroll
    for (int pr = 0; pr < 4; pr++)
#pragma unroll
        for (int c = 0; c < 4; c++)
            acc[pr][c] = pk2(bs[c0+c], bs[c0+c]);

    for (int kt = 0; kt < 8; kt++) {
        __syncthreads();   // previous compute done before overwriting xs
#pragma unroll
        for (int p = 0; p < 4; p++) {
            int row = lr + p*64;
            xs[(q*4+0)*RS + row] = nx[p].x;
            xs[(q*4+1)*RS + row] = nx[p].y;
            xs[(q*4+2)*RS + row] = nx[p].z;
            xs[(q*4+3)*RS + row] = nx[p].w;
        }
        __syncthreads();
        if (kt < 7) {
#pragma unroll
            for (int p = 0; p < 4; p++)
                nx[p] = *(const float4*)&x[(size_t)(row0 + lr + p*64)*FIN + (kt+1)*16 + q*4];
        }
#pragma unroll
        for (int k = 0; k < 16; k++) {
            float4 wv = *(const float4*)&ws[(kt*16 + k)*H + c0];
            float4 xa = *(const float4*)&xs[k*RS + r0];
            float4 xb = *(const float4*)&xs[k*RS + r0 + 4];
            unsigned long long xp[4], wp[4];
            xp[0] = pk2(xa.x, xa.y); xp[1] = pk2(xa.z, xa.w);
            xp[2] = pk2(xb.x, xb.y); xp[3] = pk2(xb.z, xb.w);
            wp[0] = pk2(wv.x, wv.x); wp[1] = pk2(wv.y, wv.y);
            wp[2] = pk2(wv.z, wv.z); wp[3] = pk2(wv.w, wv.w);
#pragma unroll
            for (int pr = 0; pr < 4; pr++) {
                fma2(acc[pr][0], xp[pr], wp[0]);
                fma2(acc[pr][1], xp[pr], wp[1]);
                fma2(acc[pr][2], xp[pr], wp[2]);
                fma2(acc[pr][3], xp[pr], wp[3]);
            }
        }
    }

#pragma unroll
    for (int pr = 0; pr < 4; pr++) {
        float lo[4], hi[4];
#pragma unroll
        for (int c = 0; c < 4; c++) upk2(lo[c], hi[c], acc[pr][c]);
        int gr = row0 + r0 + 2*pr;
        *(float4*)&g_h1[(size_t)gr*H + c0]     = make_float4(lo[0], lo[1], lo[2], lo[3]);
        *(float4*)&g_h1[(size_t)(gr+1)*H + c0] = make_float4(hi[0], hi[1], hi[2], hi[3]);
    }
}

// ---------------- mega-kernel shared layout ----------------
struct SMem {
    float h1[N*H];            // 32768 B
    float s[N*K];             // 16384 B
    float buf[2048];          // 8192  B (reduction scratch / m1 / h2)
    float wr[H*WSTR];         // Wrel transposed [lane][k]
    float wo[H*WSTR];
    float wp[K*WSTR];
    float aggb[8*32];         // per-warp agg row (broadcast source)
    float hcb[8*32];          // per-warp hc row
    float br[H];
    float bp[K];
    float px[K*H];
    float adj[K*K];
    float ssm[K*K];
    float red[32];
    float tbuf[8*16];
    float sd[K];
    float sr[H];
    float sh3[H];
    float so[FOUT];
    unsigned short idx[E_PER];
    int deg[N];
    int start[N];
    int cnt[N];
};

// ---------------- mega: everything after lin1, one CTA per graph ----------------
__global__ __launch_bounds__(256, 2)
void k_mega(const int* __restrict__ ei,
            const float* __restrict__ Wrel,  const float* __restrict__ brel,
            const float* __restrict__ Wroot, const float* __restrict__ Wpool,
            const float* __restrict__ bpool,
            const float* __restrict__ Wrel2, const float* __restrict__ brel2,
            const float* __restrict__ Wroot2,
            const float* __restrict__ Wlin2, const float* __restrict__ blin2,
            const float* __restrict__ Wlin3, const float* __restrict__ blin3,
            float* __restrict__ out)
{
    extern __shared__ char smraw[];
    SMem* sm = (SMem*)smraw;
    int b = blockIdx.x, tid = threadIdx.x;
    int w = tid >> 5, lane = tid & 31;
    int base = b * N;

    // ---- stage h1 + weights ----
    {
        const float4* gh4 = ((const float4*)g_h1) + (size_t)b*N*8;
        float4* sh4 = (float4*)sm->h1;
        for (int i = tid; i < N*8; i += 256) sh4[i] = gh4[i];
    }
    for (int i = tid; i < H*H; i += 256) {
        int k = i >> 5, l = i & 31;
        sm->wr[l*WSTR + k] = Wrel[i];
        sm->wo[l*WSTR + k] = Wroot[i];
    }
    for (int i = tid; i < H*K; i += 256) {
        int k = i >> 4, l = i & 15;
        sm->wp[l*WSTR + k] = Wpool[i];
    }
    if (tid < H) sm->br[tid] = brel[tid];
    if (tid < K) sm->bp[tid] = bpool[tid];
    sm->cnt[tid] = 0;
    __syncthreads();

    // ---- sort edges by src ----
    const int* src = ei + b*E_PER;
    const int* dst = ei + ET + b*E_PER;
#pragma unroll
    for (int i = 0; i < E_PER/256; i++)
        atomicAdd(&sm->cnt[src[tid + i*256] - base], 1);
    __syncthreads();
    int d0 = sm->cnt[tid];
    sm->start[tid] = d0;
    __syncthreads();
    for (int off = 1; off < N; off <<= 1) {
        int v = (tid >= off) ? sm->start[tid - off] : 0;
        __syncthreads();
        sm->start[tid] += v;
        __syncthreads();
    }
    int st0 = sm->start[tid] - d0;
    sm->deg[tid] = d0;
    sm->start[tid] = st0;
    sm->cnt[tid] = st0;
    __syncthreads();
#pragma unroll
    for (int i = 0; i < E_PER/256; i++) {
        int u = src[tid + i*256] - base;
        int p = atomicAdd(&sm->cnt[u], 1);
        sm->idx[p] = (unsigned short)(dst[tid + i*256] - base);
    }
    __syncthreads();

    // ---- Phase A ----
    float px_reg[16];
#pragma unroll
    for (int k = 0; k < 16; k++) px_reg[k] = 0.f;

    {
        int grp = lane >> 3, q8 = lane & 7;
        const float4* h1r = (const float4*)sm->h1;
        for (int u = w*32; u < w*32 + 32; u++) {
            int d  = sm->deg[u];
            int st = sm->start[u];
            float4 a = make_float4(0.f, 0.f, 0.f, 0.f);
            for (int i = grp; i < d; i += 4) {
                int v = sm->idx[st + i];
                float4 r = h1r[v*8 + q8];
                a.x += r.x; a.y += r.y; a.z += r.z; a.w += r.w;
            }
            a.x += __shfl_xor_sync(FULL, a.x, 8); a.x += __shfl_xor_sync(FULL, a.x, 16);
            a.y += __shfl_xor_sync(FULL, a.y, 8); a.y += __shfl_xor_sync(FULL, a.y, 16);
            a.z += __shfl_xor_sync(FULL, a.z, 8); a.z += __shfl_xor_sync(FULL, a.z, 16);
            a.w += __shfl_xor_sync(FULL, a.w, 8); a.w += __shfl_xor_sync(FULL, a.w, 16);
            if (lane < 8) *(float4*)&sm->aggb[w*32 + lane*4] = a;
            __syncwarp();

            float o = sm->br[lane];
#pragma unroll
            for (int c = 0; c < 8; c++) {
                float4 wrv = *(const float4*)&sm->wr[lane*WSTR + 4*c];
                float4 wov = *(const float4*)&sm->wo[lane*WSTR + 4*c];
                float4 av  = *(const float4*)&sm->aggb[w*32 + 4*c];     // broadcast
                float4 hv  = *(const float4*)&sm->h1[u*32 + 4*c];       // broadcast
                o += av.x*wrv.x + hv.x*wov.x;
                o += av.y*wrv.y + hv.y*wov.y;
                o += av.z*wrv.z + hv.z*wov.z;
                o += av.w*wrv.w + hv.w*wov.w;
            }
            sm->hcb[w*32 + lane] = o;
            __syncwarp();

            // pool logits + softmax over K=16
            int lk = lane & 15;
            float sl = sm->bp[lk];
#pragma unroll
            for (int c = 0; c < 8; c++) {
                float4 wpv = *(const float4*)&sm->wp[lk*WSTR + 4*c];
                float4 hq  = *(const float4*)&sm->hcb[w*32 + 4*c];      // broadcast
                sl += hq.x*wpv.x + hq.y*wpv.y + hq.z*wpv.z + hq.w*wpv.w;
            }
            float m = sl;
#pragma unroll
            for (int off = 8; off >= 1; off >>= 1)
                m = fmaxf(m, __shfl_xor_sync(FULL, m, off, 16));
            float e = expf(sl - m);
            float sum = e;
#pragma unroll
            for (int off = 8; off >= 1; off >>= 1)
                sum += __shfl_xor_sync(FULL, sum, off, 16);
            float sv = e / sum;
            if (lane < 16) sm->s[u*16 + lk] = sv;

#pragma unroll
            for (int k = 0; k < 16; k++) {
                float sk = __shfl_sync(FULL, sv, k);
                px_reg[k] += sk * o;
            }
        }
    }
    __syncthreads();

    // ---- px reduction across 8 warps ----
    for (int round = 0; round < 2; round++) {
        if ((w >> 2) == round) {
            int wl = w & 3;
#pragma unroll
            for (int k = 0; k < 16; k++)
                sm->buf[wl*512 + k*32 + lane] = px_reg[k];
        }
        __syncthreads();
        for (int i = tid; i < 512; i += 256) {
            float v = sm->buf[i] + sm->buf[512+i] + sm->buf[1024+i] + sm->buf[1536+i];
            if (round == 0) sm->px[i] = v; else sm->px[i] += v;
        }
        __syncthreads();
    }

    // ---- Phase B: t = A@s; out_adj = s^T t, ss = s^T s, den ----
    float oa[8], ob[8];
#pragma unroll
    for (int i = 0; i < 8; i++) { oa[i] = 0.f; ob[i] = 0.f; }
    float den_acc = 0.f;
    {
        int grp8 = lane >> 2, q4 = lane & 3;
        int j = lane & 15, kh = lane >> 4;
        const float4* ssr = (const float4*)sm->s;
        for (int u = w*32; u < w*32 + 32; u++) {
            int d  = sm->deg[u];
            int st = sm->start[u];
            float4 a = make_float4(0.f, 0.f, 0.f, 0.f);
            for (int i = grp8; i < d; i += 8) {
                int v = sm->idx[st + i];
                float4 r = ssr[v*4 + q4];
                a.x += r.x; a.y += r.y; a.z += r.z; a.w += r.w;
            }
            a.x += __shfl_xor_sync(FULL, a.x, 4); a.x += __shfl_xor_sync(FULL, a.x, 8); a.x += __shfl_xor_sync(FULL, a.x, 16);
            a.y += __shfl_xor_sync(FULL, a.y, 4); a.y += __shfl_xor_sync(FULL, a.y, 8); a.y += __shfl_xor_sync(FULL, a.y, 16);
            a.z += __shfl_xor_sync(FULL, a.z, 4); a.z += __shfl_xor_sync(FULL, a.z, 8); a.z += __shfl_xor_sync(FULL, a.z, 16);
            a.w += __shfl_xor_sync(FULL, a.w, 4); a.w += __shfl_xor_sync(FULL, a.w, 8); a.w += __shfl_xor_sync(FULL, a.w, 16);
            if (lane < 4) *(float4*)&sm->tbuf[w*16 + lane*4] = a;
            __syncwarp();
            float tj = sm->tbuf[w*16 + j];
            float sj = sm->s[u*16 + j];
            __syncwarp();

            float v2 = sj*sj;
            v2 += __shfl_xor_sync(FULL, v2, 1, 16);
            v2 += __shfl_xor_sync(FULL, v2, 2, 16);
            v2 += __shfl_xor_sync(FULL, v2, 4, 16);
            v2 += __shfl_xor_sync(FULL, v2, 8, 16);
            den_acc += (float)d * v2;

#pragma unroll
            for (int kk = 0; kk < 8; kk++) {
                float su = sm->s[u*16 + kh*8 + kk];
                oa[kk] += su * tj;
                ob[kk] += su * sj;
            }
        }
    }
    __syncthreads();

    // ---- reduce out_adj, ss, den across warps ----
    {
        int j = lane & 15, kh = lane >> 4;
#pragma unroll
        for (int kk = 0; kk < 8; kk++)
            sm->buf[w*256 + (kh*8+kk)*16 + j] = oa[kk];
        if (lane == 0) sm->red[w] = den_acc;
        __syncthreads();
        float v = 0.f;
#pragma unroll
        for (int ww = 0; ww < 8; ww++) v += sm->buf[ww*256 + tid];
        sm->adj[tid] = v;
        __syncthreads();
#pragma unroll
        for (int kk = 0; kk < 8; kk++)
            sm->buf[w*256 + (kh*8+kk)*16 + j] = ob[kk];
        __syncthreads();
        float v2 = 0.f;
#pragma unroll
        for (int ww = 0; ww < 8; ww++) v2 += sm->buf[ww*256 + tid];
        sm->ssm[tid] = v2;
        __syncthreads();
    }

    // ---- losses ----
    int kq = tid >> 4, jq = tid & 15;
    if (tid == 0) {
        float den = 0.f;
        for (int i = 0; i < 8; i++) den += sm->red[i];
        float num = 0.f;
        for (int kk = 0; kk < K; kk++) num += sm->adj[kk*K + kk];
        g_loss[b] = -(num / den);
    }
    float ssv = sm->ssm[tid];
    sm->buf[tid] = ssv * ssv;
    __syncthreads();
    for (int off = 128; off > 0; off >>= 1) { if (tid < off) sm->buf[tid] += sm->buf[tid + off]; __syncthreads(); }
    float nrm = sqrtf(sm->buf[0]);
    __syncthreads();
    float diff = ssv / nrm - ((kq == jq) ? 0.25f : 0.f);
    sm->buf[tid] = diff * diff;
    __syncthreads();
    for (int off = 128; off > 0; off >>= 1) { if (tid < off) sm->buf[tid] += sm->buf[tid + off]; __syncthreads(); }
    if (tid == 0) g_loss[B + b] = sqrtf(sm->buf[0]);
    __syncthreads();

    // ---- normalize out_adj ----
    {
        float av = (kq == jq) ? 0.f : sm->adj[tid];
        sm->adj[tid] = av;
    }
    __syncthreads();
    if (tid < K) {
        float rs = 0.f;
        for (int jj = 0; jj < K; jj++) rs += sm->adj[tid*K + jj];
        sm->sd[tid] = sqrtf(rs) + EPSF;
    }
    __syncthreads();
    sm->adj[tid] = sm->adj[tid] / (sm->sd[kq] * sm->sd[jq]);
    __syncthreads();

    // ---- conv2 on pooled features ----
    {
        int h = tid & 31, kk0 = tid >> 5;
#pragma unroll
        for (int rep = 0; rep < 2; rep++) {
            int kc = kk0 + rep*8;
            float m1 = 0.f;
#pragma unroll
            for (int jj = 0; jj < K; jj++) m1 += sm->adj[kc*K + jj] * sm->px[jj*H + h];
            sm->buf[kc*H + h] = m1;
        }
    }
    __syncthreads();
    {
        int h = tid & 31, kk0 = tid >> 5;
#pragma unroll
        for (int rep = 0; rep < 2; rep++) {
            int kc = kk0 + rep*8;
            float acc = brel2[h];
            for (int c = 0; c < H; c++)
                acc += sm->buf[kc*H + c] * Wrel2[c*H + h] + sm->px[kc*H + c] * Wroot2[c*H + h];
            sm->buf[512 + kc*H + h] = acc;
        }
    }
    __syncthreads();

    // ---- readout + MLP + log_softmax ----
    if (tid < H) {
        float r = 0.f;
#pragma unroll
        for (int kk = 0; kk < K; kk++) r += sm->buf[512 + kk*H + tid];
        sm->sr[tid] = r;
    }
    __syncthreads();
    if (tid < H) {
        float a2 = blin2[tid];
        for (int c = 0; c < H; c++) a2 += sm->sr[c] * Wlin2[c*H + tid];
        sm->sh3[tid] = fmaxf(a2, 0.f);
    }
    __syncthreads();
    if (tid < FOUT) {
        float a3 = blin3[tid];
        for (int c = 0; c < H; c++) a3 += sm->sh3[c] * Wlin3[c*FOUT + tid];
        sm->so[tid] = a3;
    }
    __syncthreads();
    if (tid == 0) {
        float m = sm->so[0];
        for (int i = 1; i < FOUT; i++) m = fmaxf(m, sm->so[i]);
        float s = 0.f;
        for (int i = 0; i < FOUT; i++) s += expf(sm->so[i] - m);
        float lse = m + logf(s);
        for (int i = 0; i < FOUT; i++) out[b*FOUT + i] = sm->so[i] - lse;
    }
}

__global__ void k_final(float* __restrict__ out, int out_size) {
    __shared__ float s1[B], s2[B];
    int t = threadIdx.x;
    s1[t] = g_loss[t];
    s2[t] = g_loss[B + t];
    __syncthreads();
    for (int off = 256; off > 0; off >>= 1) {
        if (t < off) { s1[t] += s1[t + off]; s2[t] += s2[t + off]; }
        __syncthreads();
    }
    if (t == 0) {
        if (out_size > B*FOUT)     out[B*FOUT]     = s1[0] / (float)B;
        if (out_size > B*FOUT + 1) out[B*FOUT + 1] = s2[0] / (float)B;
    }
}

// ---------------- launch ----------------
extern "C" void kernel_launch(void* const* d_in, const int* in_sizes, int n_in,
                              void* d_out, int out_size) {
    const float* x     = (const float*)d_in[0];
    const int*   ei    = (const int*)d_in[1];
    const float* Wlin1 = (const float*)d_in[3];
    const float* blin1 = (const float*)d_in[4];
    const float* Wrel1 = (const float*)d_in[5];
    const float* brel1 = (const float*)d_in[6];
    const float* Wroot1= (const float*)d_in[7];
    const float* Wpool = (const float*)d_in[8];
    const float* bpool = (const float*)d_in[9];
    const float* Wrel2 = (const float*)d_in[10];
    const float* brel2 = (const float*)d_in[11];
    const float* Wroot2= (const float*)d_in[12];
    const float* Wlin2 = (const float*)d_in[13];
    const float* blin2 = (const float*)d_in[14];
    const float* Wlin3 = (const float*)d_in[15];
    const float* blin3 = (const float*)d_in[16];
    float* out = (float*)d_out;

    cudaFuncSetAttribute(k_mega, cudaFuncAttributeMaxDynamicSharedMemorySize,
                         (int)sizeof(SMem));

    k_lin1<<<NT/256, 256>>>(x, Wlin1, blin1);
    k_mega<<<B, 256, sizeof(SMem)>>>(ei, Wrel1, brel1, Wroot1, Wpool, bpool,
                                     Wrel2, brel2, Wroot2,
                                     Wlin2, blin2, Wlin3, blin3, out);
    k_final<<<1, B>>>(out, out_size);
}

// round 7
// speedup vs baseline: 2.0935x; 1.0570x over previous
#include <cuda_runtime.h>

#define B 512
#define N 256
#define E_PER 8192
#define NT (B*N)
#define ET (B*E_PER)
#define FIN 128
#define H 32
#define K 16
#define FOUT 10
#define EPSF 1e-15f
#define FULL 0xffffffffu
#define WSTR 36         // padded transposed-weight stride
#define RS   260        // xs transpose stride

// ---------------- globals ----------------
__device__ float g_loss[2*B];

// ---------------- f32x2 helpers ----------------
__device__ __forceinline__ unsigned long long pk2(float lo, float hi) {
    unsigned long long r;
    asm("mov.b64 %0, {%1,%2};" : "=l"(r)
        : "r"(__float_as_uint(lo)), "r"(__float_as_uint(hi)));
    return r;
}
__device__ __forceinline__ void fma2(unsigned long long& d,
                                     unsigned long long a, unsigned long long b) {
    asm("fma.rn.f32x2 %0, %1, %2, %0;" : "+l"(d) : "l"(a), "l"(b));
}
__device__ __forceinline__ void upk2(float& lo, float& hi, unsigned long long v) {
    unsigned int a, b2;
    asm("mov.b64 {%0,%1}, %2;" : "=r"(a), "=r"(b2) : "l"(v));
    lo = __uint_as_float(a); hi = __uint_as_float(b2);
}

// ---------------- mega-kernel shared layout ----------------
struct SMem {
    float h1[N*H];            // 32768 B
    float s[N*K];             // 16384 B (overlaid by ws[FIN*H] during lin1)
    float buf[2048];          // 8192  B
    float wr[H*WSTR];
    float wo[H*WSTR];
    float wp[K*WSTR];
    float aggb[8*32];
    float hcb[8*32];
    float br[H];
    float bp[K];
    float px[K*H];
    float adj[K*K];
    float ssm[K*K];
    float red[32];
    float tbuf[8*16];
    float sd[K];
    float sr[H];
    float sh3[H];
    float so[FOUT];
    alignas(16) unsigned short idx[E_PER];  // overlaid by xs[16*RS] during lin1
    int deg[N];
    int start[N];
    int cnt[N];
};

// ---------------- mega: entire network, one CTA per graph ----------------
__global__ __launch_bounds__(256, 2)
void k_mega(const float* __restrict__ x,
            const int* __restrict__ ei,
            const float* __restrict__ Wlin1, const float* __restrict__ blin1,
            const float* __restrict__ Wrel,  const float* __restrict__ brel,
            const float* __restrict__ Wroot, const float* __restrict__ Wpool,
            const float* __restrict__ bpool,
            const float* __restrict__ Wrel2, const float* __restrict__ brel2,
            const float* __restrict__ Wroot2,
            const float* __restrict__ Wlin2, const float* __restrict__ blin2,
            const float* __restrict__ Wlin3, const float* __restrict__ blin3,
            float* __restrict__ out)
{
    extern __shared__ char smraw[];
    SMem* sm = (SMem*)smraw;
    int b = blockIdx.x, tid = threadIdx.x;
    int w = tid >> 5, lane = tid & 31;
    int base = b * N;

    // ================= fused lin1: h1 = x[b] @ W1 + b1 (FFMA2 tile) ==========
    {
        float* ws = sm->s;                 // overlay (s dead until phase A)
        float* xs = (float*)sm->idx;       // overlay (idx dead until sort)
        for (int i = tid; i < FIN*H; i += 256) ws[i] = Wlin1[i];

        int c0 = (tid & 7) * 4;            // 4 output cols
        int r0 = (tid >> 3) * 8;           // 8 output rows
        int lr = tid >> 2;                 // staging row
        int q  = tid & 3;                  // staging k-quad

        float bsv[4];
#pragma unroll
        for (int c = 0; c < 4; c++) bsv[c] = blin1[c0 + c];

        const float* xg = x + (size_t)base * FIN;
        float4 nx[4];
#pragma unroll
        for (int p = 0; p < 4; p++)
            nx[p] = *(const float4*)&xg[(size_t)(lr + p*64)*FIN + q*4];

        unsigned long long acc[4][4];
#pragma unroll
        for (int pr = 0; pr < 4; pr++)
#pragma unroll
            for (int c = 0; c < 4; c++)
                acc[pr][c] = pk2(bsv[c], bsv[c]);

        for (int kt = 0; kt < 8; kt++) {
            __syncthreads();               // (kt=0: also guards ws staging)
#pragma unroll
            for (int p = 0; p < 4; p++) {
                int row = lr + p*64;
                xs[(q*4+0)*RS + row] = nx[p].x;
                xs[(q*4+1)*RS + row] = nx[p].y;
                xs[(q*4+2)*RS + row] = nx[p].z;
                xs[(q*4+3)*RS + row] = nx[p].w;
            }
            __syncthreads();
            if (kt < 7) {
#pragma unroll
                for (int p = 0; p < 4; p++)
                    nx[p] = *(const float4*)&xg[(size_t)(lr + p*64)*FIN + (kt+1)*16 + q*4];
            }
#pragma unroll
            for (int k = 0; k < 16; k++) {
                float4 wv = *(const float4*)&ws[(kt*16 + k)*H + c0];
                float4 xa = *(const float4*)&xs[k*RS + r0];
                float4 xb = *(const float4*)&xs[k*RS + r0 + 4];
                unsigned long long xp[4], wp2[4];
                xp[0] = pk2(xa.x, xa.y); xp[1] = pk2(xa.z, xa.w);
                xp[2] = pk2(xb.x, xb.y); xp[3] = pk2(xb.z, xb.w);
                wp2[0] = pk2(wv.x, wv.x); wp2[1] = pk2(wv.y, wv.y);
                wp2[2] = pk2(wv.z, wv.z); wp2[3] = pk2(wv.w, wv.w);
#pragma unroll
                for (int pr = 0; pr < 4; pr++) {
                    fma2(acc[pr][0], xp[pr], wp2[0]);
                    fma2(acc[pr][1], xp[pr], wp2[1]);
                    fma2(acc[pr][2], xp[pr], wp2[2]);
                    fma2(acc[pr][3], xp[pr], wp2[3]);
                }
            }
        }
#pragma unroll
        for (int pr = 0; pr < 4; pr++) {
            float lo[4], hi[4];
#pragma unroll
            for (int c = 0; c < 4; c++) upk2(lo[c], hi[c], acc[pr][c]);
            int gr = r0 + 2*pr;
            *(float4*)&sm->h1[gr*H + c0]     = make_float4(lo[0], lo[1], lo[2], lo[3]);
            *(float4*)&sm->h1[(gr+1)*H + c0] = make_float4(hi[0], hi[1], hi[2], hi[3]);
        }
    }
    __syncthreads();   // lin1 done: xs/ws regions become idx/s again

    // ---- stage conv/pool weights (transposed, padded) ----
    for (int i = tid; i < H*H; i += 256) {
        int k = i >> 5, l = i & 31;
        sm->wr[l*WSTR + k] = Wrel[i];
        sm->wo[l*WSTR + k] = Wroot[i];
    }
    for (int i = tid; i < H*K; i += 256) {
        int k = i >> 4, l = i & 15;
        sm->wp[l*WSTR + k] = Wpool[i];
    }
    if (tid < H) sm->br[tid] = brel[tid];
    if (tid < K) sm->bp[tid] = bpool[tid];
    sm->cnt[tid] = 0;
    __syncthreads();

    // ---- sort edges by src ----
    const int* src = ei + b*E_PER;
    const int* dst = ei + ET + b*E_PER;
#pragma unroll
    for (int i = 0; i < E_PER/256; i++)
        atomicAdd(&sm->cnt[src[tid + i*256] - base], 1);
    __syncthreads();
    int d0 = sm->cnt[tid];
    sm->start[tid] = d0;
    __syncthreads();
    for (int off = 1; off < N; off <<= 1) {
        int v = (tid >= off) ? sm->start[tid - off] : 0;
        __syncthreads();
        sm->start[tid] += v;
        __syncthreads();
    }
    int st0 = sm->start[tid] - d0;
    sm->deg[tid] = d0;
    sm->start[tid] = st0;
    sm->cnt[tid] = st0;
    __syncthreads();
#pragma unroll
    for (int i = 0; i < E_PER/256; i++) {
        int u = src[tid + i*256] - base;
        int p = atomicAdd(&sm->cnt[u], 1);
        sm->idx[p] = (unsigned short)(dst[tid + i*256] - base);
    }
    __syncthreads();

    // ---- Phase A: gather agg, conv1, pool, softmax, px rank-1 ----
    float px_reg[16];
#pragma unroll
    for (int k = 0; k < 16; k++) px_reg[k] = 0.f;

    {
        int grp = lane >> 3, q8 = lane & 7;
        const float4* h1r = (const float4*)sm->h1;
        for (int u = w*32; u < w*32 + 32; u++) {
            int d  = sm->deg[u];
            int st = sm->start[u];
            float4 a = make_float4(0.f, 0.f, 0.f, 0.f);
            for (int i = grp; i < d; i += 4) {
                int v = sm->idx[st + i];
                float4 r = h1r[v*8 + q8];
                a.x += r.x; a.y += r.y; a.z += r.z; a.w += r.w;
            }
            a.x += __shfl_xor_sync(FULL, a.x, 8); a.x += __shfl_xor_sync(FULL, a.x, 16);
            a.y += __shfl_xor_sync(FULL, a.y, 8); a.y += __shfl_xor_sync(FULL, a.y, 16);
            a.z += __shfl_xor_sync(FULL, a.z, 8); a.z += __shfl_xor_sync(FULL, a.z, 16);
            a.w += __shfl_xor_sync(FULL, a.w, 8); a.w += __shfl_xor_sync(FULL, a.w, 16);
            if (lane < 8) *(float4*)&sm->aggb[w*32 + lane*4] = a;
            __syncwarp();

            float o = sm->br[lane];
#pragma unroll
            for (int c = 0; c < 8; c++) {
                float4 wrv = *(const float4*)&sm->wr[lane*WSTR + 4*c];
                float4 wov = *(const float4*)&sm->wo[lane*WSTR + 4*c];
                float4 av  = *(const float4*)&sm->aggb[w*32 + 4*c];
                float4 hv  = *(const float4*)&sm->h1[u*32 + 4*c];
                o += av.x*wrv.x + hv.x*wov.x;
                o += av.y*wrv.y + hv.y*wov.y;
                o += av.z*wrv.z + hv.z*wov.z;
                o += av.w*wrv.w + hv.w*wov.w;
            }
            sm->hcb[w*32 + lane] = o;
            __syncwarp();

            int lk = lane & 15;
            float sl = sm->bp[lk];
#pragma unroll
            for (int c = 0; c < 8; c++) {
                float4 wpv = *(const float4*)&sm->wp[lk*WSTR + 4*c];
                float4 hq  = *(const float4*)&sm->hcb[w*32 + 4*c];
                sl += hq.x*wpv.x + hq.y*wpv.y + hq.z*wpv.z + hq.w*wpv.w;
            }
            float m = sl;
#pragma unroll
            for (int off = 8; off >= 1; off >>= 1)
                m = fmaxf(m, __shfl_xor_sync(FULL, m, off, 16));
            float e = expf(sl - m);
            float sum = e;
#pragma unroll
            for (int off = 8; off >= 1; off >>= 1)
                sum += __shfl_xor_sync(FULL, sum, off, 16);
            float sv = e / sum;
            if (lane < 16) sm->s[u*16 + lk] = sv;

#pragma unroll
            for (int k = 0; k < 16; k++) {
                float sk = __shfl_sync(FULL, sv, k);
                px_reg[k] += sk * o;
            }
        }
    }
    __syncthreads();

    // ---- px reduction across 8 warps ----
    for (int round = 0; round < 2; round++) {
        if ((w >> 2) == round) {
            int wl = w & 3;
#pragma unroll
            for (int k = 0; k < 16; k++)
                sm->buf[wl*512 + k*32 + lane] = px_reg[k];
        }
        __syncthreads();
        for (int i = tid; i < 512; i += 256) {
            float v = sm->buf[i] + sm->buf[512+i] + sm->buf[1024+i] + sm->buf[1536+i];
            if (round == 0) sm->px[i] = v; else sm->px[i] += v;
        }
        __syncthreads();
    }

    // ---- Phase B: t = A@s; out_adj = s^T t, ss = s^T s, den ----
    float oa[8], ob[8];
#pragma unroll
    for (int i = 0; i < 8; i++) { oa[i] = 0.f; ob[i] = 0.f; }
    float den_acc = 0.f;
    {
        int grp8 = lane >> 2, q4 = lane & 3;
        int j = lane & 15, kh = lane >> 4;
        const float4* ssr = (const float4*)sm->s;
        for (int u = w*32; u < w*32 + 32; u++) {
            int d  = sm->deg[u];
            int st = sm->start[u];
            float4 a = make_float4(0.f, 0.f, 0.f, 0.f);
            for (int i = grp8; i < d; i += 8) {
                int v = sm->idx[st + i];
                float4 r = ssr[v*4 + q4];
                a.x += r.x; a.y += r.y; a.z += r.z; a.w += r.w;
            }
            a.x += __shfl_xor_sync(FULL, a.x, 4); a.x += __shfl_xor_sync(FULL, a.x, 8); a.x += __shfl_xor_sync(FULL, a.x, 16);
            a.y += __shfl_xor_sync(FULL, a.y, 4); a.y += __shfl_xor_sync(FULL, a.y, 8); a.y += __shfl_xor_sync(FULL, a.y, 16);
            a.z += __shfl_xor_sync(FULL, a.z, 4); a.z += __shfl_xor_sync(FULL, a.z, 8); a.z += __shfl_xor_sync(FULL, a.z, 16);
            a.w += __shfl_xor_sync(FULL, a.w, 4); a.w += __shfl_xor_sync(FULL, a.w, 8); a.w += __shfl_xor_sync(FULL, a.w, 16);
            if (lane < 4) *(float4*)&sm->tbuf[w*16 + lane*4] = a;
            __syncwarp();
            float tj = sm->tbuf[w*16 + j];
            float sj = sm->s[u*16 + j];
            __syncwarp();

            float v2 = sj*sj;
            v2 += __shfl_xor_sync(FULL, v2, 1, 16);
            v2 += __shfl_xor_sync(FULL, v2, 2, 16);
            v2 += __shfl_xor_sync(FULL, v2, 4, 16);
            v2 += __shfl_xor_sync(FULL, v2, 8, 16);
            den_acc += (float)d * v2;

#pragma unroll
            for (int kk = 0; kk < 8; kk++) {
                float su = sm->s[u*16 + kh*8 + kk];
                oa[kk] += su * tj;
                ob[kk] += su * sj;
            }
        }
    }
    __syncthreads();

    // ---- reduce out_adj, ss, den across warps ----
    {
        int j = lane & 15, kh = lane >> 4;
#pragma unroll
        for (int kk = 0; kk < 8; kk++)
            sm->buf[w*256 + (kh*8+kk)*16 + j] = oa[kk];
        if (lane == 0) sm->red[w] = den_acc;
        __syncthreads();
        float v = 0.f;
#pragma unroll
        for (int ww = 0; ww < 8; ww++) v += sm->buf[ww*256 + tid];
        sm->adj[tid] = v;
        __syncthreads();
#pragma unroll
        for (int kk = 0; kk < 8; kk++)
            sm->buf[w*256 + (kh*8+kk)*16 + j] = ob[kk];
        __syncthreads();
        float v2 = 0.f;
#pragma unroll
        for (int ww = 0; ww < 8; ww++) v2 += sm->buf[ww*256 + tid];
        sm->ssm[tid] = v2;
        __syncthreads();
    }

    // ---- losses ----
    int kq = tid >> 4, jq = tid & 15;
    if (tid == 0) {
        float den = 0.f;
        for (int i = 0; i < 8; i++) den += sm->red[i];
        float num = 0.f;
        for (int kk = 0; kk < K; kk++) num += sm->adj[kk*K + kk];
        g_loss[b] = -(num / den);
    }
    float ssv = sm->ssm[tid];
    sm->buf[tid] = ssv * ssv;
    __syncthreads();
    for (int off = 128; off > 0; off >>= 1) { if (tid < off) sm->buf[tid] += sm->buf[tid + off]; __syncthreads(); }
    float nrm = sqrtf(sm->buf[0]);
    __syncthreads();
    float diff = ssv / nrm - ((kq == jq) ? 0.25f : 0.f);
    sm->buf[tid] = diff * diff;
    __syncthreads();
    for (int off = 128; off > 0; off >>= 1) { if (tid < off) sm->buf[tid] += sm->buf[tid + off]; __syncthreads(); }
    if (tid == 0) g_loss[B + b] = sqrtf(sm->buf[0]);
    __syncthreads();

    // ---- normalize out_adj ----
    {
        float av = (kq == jq) ? 0.f : sm->adj[tid];
        sm->adj[tid] = av;
    }
    __syncthreads();
    if (tid < K) {
        float rs = 0.f;
        for (int jj = 0; jj < K; jj++) rs += sm->adj[tid*K + jj];
        sm->sd[tid] = sqrtf(rs) + EPSF;
    }
    __syncthreads();
    sm->adj[tid] = sm->adj[tid] / (sm->sd[kq] * sm->sd[jq]);
    __syncthreads();

    // ---- conv2 on pooled features ----
    {
        int h = tid & 31, kk0 = tid >> 5;
#pragma unroll
        for (int rep = 0; rep < 2; rep++) {
            int kc = kk0 + rep*8;
            float m1 = 0.f;
#pragma unroll
            for (int jj = 0; jj < K; jj++) m1 += sm->adj[kc*K + jj] * sm->px[jj*H + h];
            sm->buf[kc*H + h] = m1;
        }
    }
    __syncthreads();
    {
        int h = tid & 31, kk0 = tid >> 5;
#pragma unroll
        for (int rep = 0; rep < 2; rep++) {
            int kc = kk0 + rep*8;
            float acc = brel2[h];
            for (int c = 0; c < H; c++)
                acc += sm->buf[kc*H + c] * Wrel2[c*H + h] + sm->px[kc*H + c] * Wroot2[c*H + h];
            sm->buf[512 + kc*H + h] = acc;
        }
    }
    __syncthreads();

    // ---- readout + MLP + log_softmax ----
    if (tid < H) {
        float r = 0.f;
#pragma unroll
        for (int kk = 0; kk < K; kk++) r += sm->buf[512 + kk*H + tid];
        sm->sr[tid] = r;
    }
    __syncthreads();
    if (tid < H) {
        float a2 = blin2[tid];
        for (int c = 0; c < H; c++) a2 += sm->sr[c] * Wlin2[c*H + tid];
        sm->sh3[tid] = fmaxf(a2, 0.f);
    }
    __syncthreads();
    if (tid < FOUT) {
        float a3 = blin3[tid];
        for (int c = 0; c < H; c++) a3 += sm->sh3[c] * Wlin3[c*FOUT + tid];
        sm->so[tid] = a3;
    }
    __syncthreads();
    if (tid == 0) {
        float m = sm->so[0];
        for (int i = 1; i < FOUT; i++) m = fmaxf(m, sm->so[i]);
        float s = 0.f;
        for (int i = 0; i < FOUT; i++) s += expf(sm->so[i] - m);
        float lse = m + logf(s);
        for (int i = 0; i < FOUT; i++) out[b*FOUT + i] = sm->so[i] - lse;
    }
}

__global__ void k_final(float* __restrict__ out, int out_size) {
    __shared__ float s1[B], s2[B];
    int t = threadIdx.x;
    s1[t] = g_loss[t];
    s2[t] = g_loss[B + t];
    __syncthreads();
    for (int off = 256; off > 0; off >>= 1) {
        if (t < off) { s1[t] += s1[t + off]; s2[t] += s2[t + off]; }
        __syncthreads();
    }
    if (t == 0) {
        if (out_size > B*FOUT)     out[B*FOUT]     = s1[0] / (float)B;
        if (out_size > B*FOUT + 1) out[B*FOUT + 1] = s2[0] / (float)B;
    }
}

// ---------------- launch ----------------
extern "C" void kernel_launch(void* const* d_in, const int* in_sizes, int n_in,
                              void* d_out, int out_size) {
    const float* x     = (const float*)d_in[0];
    const int*   ei    = (const int*)d_in[1];
    const float* Wlin1 = (const float*)d_in[3];
    const float* blin1 = (const float*)d_in[4];
    const float* Wrel1 = (const float*)d_in[5];
    const float* brel1 = (const float*)d_in[6];
    const float* Wroot1= (const float*)d_in[7];
    const float* Wpool = (const float*)d_in[8];
    const float* bpool = (const float*)d_in[9];
    const float* Wrel2 = (const float*)d_in[10];
    const float* brel2 = (const float*)d_in[11];
    const float* Wroot2= (const float*)d_in[12];
    const float* Wlin2 = (const float*)d_in[13];
    const float* blin2 = (const float*)d_in[14];
    const float* Wlin3 = (const float*)d_in[15];
    const float* blin3 = (const float*)d_in[16];
    float* out = (float*)d_out;

    cudaFuncSetAttribute(k_mega, cudaFuncAttributeMaxDynamicSharedMemorySize,
                         (int)sizeof(SMem));

    k_mega<<<B, 256, sizeof(SMem)>>>(x, ei, Wlin1, blin1,
                                     Wrel1, brel1, Wroot1, Wpool, bpool,
                                     Wrel2, brel2, Wroot2,
                                     Wlin2, blin2, Wlin3, blin3, out);
    k_final<<<1, B>>>(out, out_size);
}